// round 8
// baseline (speedup 1.0000x reference)
#include <cuda_runtime.h>

// SkelConv v8: CG=2 / U=16 reshape for 4 CTAs/SM (16 warps).
// One warp per co-pair; each thread computes 16 consecutive outputs for 2
// out-channels. Parity-shifted accumulators (no pack MOVs); x window (32
// floats) via 8 aligned LDG.128 reused across both channels.

#define C_IN   103
#define C_OUT  206
#define KK     15
#define TLEN   8192
#define NB     32
#define TPB    128
#define U      16
#define TT     512          // 32 lanes * 16
#define CG     2

typedef unsigned long long u64;

__device__ __forceinline__ u64 pack2(float lo, float hi) {
    u64 r;
    asm("mov.b64 %0, {%1, %2};" : "=l"(r) : "f"(lo), "f"(hi));
    return r;
}
__device__ __forceinline__ void unpack2(u64 v, float& lo, float& hi) {
    asm("mov.b64 {%0, %1}, %2;" : "=f"(lo), "=f"(hi) : "l"(v));
}
__device__ __forceinline__ void ffma2(u64& d, u64 a, u64 b) {
    asm("fma.rn.f32x2 %0, %1, %2, %0;" : "+l"(d) : "l"(a), "l"(b));
}

// y = 0..25: 0,1 = root halves (7 out ch each), y>=2 -> joint j=y-1 (8 out ch)
__device__ __forceinline__ void jp(int y, int& i0, int& iw, int& o0, int& ow) {
    if (y == 0)      { i0 = 0;  iw = 11; o0 = 0; ow = 7; }
    else if (y == 1) { i0 = 0;  iw = 11; o0 = 7; ow = 7; }
    else {
        const int j = y - 1;
        o0 = 14 + (j - 1) * 8; ow = 8;
        if (j == 1)       { i0 = 0;              iw = 15; }
        else if (j == 24) { i0 = 95;             iw = 8;  }
        else              { i0 = 7 + (j - 2) * 4; iw = 12; }
    }
}

__global__ void __launch_bounds__(TPB, 4)
skel_conv8_kernel(const float* __restrict__ x,
                  const float* __restrict__ w,
                  const float* __restrict__ bias,
                  const float* __restrict__ mask,
                  float* __restrict__ out)
{
    int i0, iw, o0, ow;
    jp(blockIdx.y, i0, iw, o0, ow);

    const int b   = blockIdx.z;
    const int tid = threadIdx.x;

    // wsh[ci][co][q] = {w(2q),w(2q), w(2q+1),w(2q+1)} masked (k=15 slot -> 0).
    __shared__ float4 wsh[15][8][8];
    {
        const int total = iw * 64;
        for (int idx = tid; idx < total; idx += TPB) {
            const int q  = idx & 7;
            const int co = (idx >> 3) & 7;
            const int ci = idx >> 6;
            float a = 0.0f, c = 0.0f;
            if (co < ow) {
                const int gi = ((o0 + co) * C_IN + (i0 + ci)) * KK;
                a = w[gi + 2 * q] * mask[gi + 2 * q];
                if (2 * q + 1 < KK) c = w[gi + 2 * q + 1] * mask[gi + 2 * q + 1];
            }
            wsh[ci][co][q] = make_float4(a, a, c, c);
        }
    }
    __syncthreads();

    const int g      = tid >> 5;          // warp id = co-group 0..3
    const int lane   = tid & 31;
    const int cobase = g * CG;
    const int T0     = blockIdx.x * TT + lane * U;

    // accA[c][p]: odd taps, outputs {T0+2p, T0+2p+1}, p=0..7
    // accB[c][j]: even taps, outputs {T0+2j-1, T0+2j}, j=0..8
    u64 accA[CG][8], accB[CG][9];
#pragma unroll
    for (int c = 0; c < CG; c++) {
#pragma unroll
        for (int p = 0; p < 8; p++) accA[c][p] = 0ull;
#pragma unroll
        for (int j = 0; j < 9; j++) accB[c][j] = 0ull;
    }

    const bool interior = (T0 >= 8) && (T0 + 24 <= TLEN);
    const float* base = x + (size_t)b * C_IN * TLEN;

    for (int ci = 0; ci < iw; ci++) {
        const float* xrow = base + (size_t)(i0 + ci) * TLEN;

        // xe[i] = {x[T0-8+2i], x[T0-8+2i+1]}, i = 0..15 (window [T0-8, T0+24))
        u64 xe[16];
        if (interior) {
            const ulonglong2* xq =
                reinterpret_cast<const ulonglong2*>(xrow + T0 - 8);
#pragma unroll
            for (int q = 0; q < 8; q++) {
                const ulonglong2 v = xq[q];
                xe[2 * q]     = v.x;
                xe[2 * q + 1] = v.y;
            }
        } else {
#pragma unroll
            for (int i = 0; i < 16; i++) {
                const int t = T0 - 8 + 2 * i;
                const float lo = (t >= 0 && t < TLEN) ? xrow[t] : 0.0f;
                const float hi = (t + 1 >= 0 && t + 1 < TLEN) ? xrow[t + 1] : 0.0f;
                xe[i] = pack2(lo, hi);
            }
        }

#pragma unroll
        for (int c = 0; c < CG; c++) {
            const ulonglong2* wq =
                reinterpret_cast<const ulonglong2*>(&wsh[ci][cobase + c][0]);
#pragma unroll
            for (int q = 0; q < 8; q++) {
                const ulonglong2 wv = wq[q];  // .x = dup w(2q), .y = dup w(2q+1)
                // even tap k=2q -> accB[j] uses xe[q+j], j=0..8
#pragma unroll
                for (int jj = 0; jj < 9; jj++) ffma2(accB[c][jj], wv.x, xe[q + jj]);
                // odd tap k=2q+1 (k<15) -> accA[p] uses xe[q+1+p], p=0..7
                if (q < 7) {
#pragma unroll
                    for (int p = 0; p < 8; p++) ffma2(accA[c][p], wv.y, xe[q + 1 + p]);
                }
            }
        }
    }

    // Combine parities + bias + store (16 outputs per co).
#pragma unroll
    for (int c = 0; c < CG; c++) {
        const int co = cobase + c;
        if (co < ow) {
            const float bv = bias[o0 + co];
            float* ob = out + ((size_t)b * C_OUT + (o0 + co)) * TLEN + T0;
            float aLo[8], aHi[8], bLo[9], bHi[9];
#pragma unroll
            for (int p = 0; p < 8; p++) unpack2(accA[c][p], aLo[p], aHi[p]);
#pragma unroll
            for (int j = 0; j < 9; j++) unpack2(accB[c][j], bLo[j], bHi[j]);
#pragma unroll
            for (int p = 0; p < 8; p += 2) {
                float4 r;
                r.x = aLo[p]     + bHi[p]     + bv;   // out[T0+2p]
                r.y = aHi[p]     + bLo[p + 1] + bv;   // out[T0+2p+1]
                r.z = aLo[p + 1] + bHi[p + 1] + bv;   // out[T0+2p+2]
                r.w = aHi[p + 1] + bLo[p + 2] + bv;   // out[T0+2p+3]
                *reinterpret_cast<float4*>(ob + 2 * p) = r;
            }
        }
    }
}

extern "C" void kernel_launch(void* const* d_in, const int* in_sizes, int n_in,
                              void* d_out, int out_size)
{
    (void)in_sizes; (void)n_in; (void)out_size;
    const float* x    = (const float*)d_in[0];
    const float* w    = (const float*)d_in[1];
    const float* bias = (const float*)d_in[2];
    const float* mask = (const float*)d_in[3];
    float* out = (float*)d_out;

    dim3 grid(TLEN / TT, 26, NB);
    skel_conv8_kernel<<<grid, TPB>>>(x, w, bias, mask, out);
}

// round 9
// speedup vs baseline: 1.0392x; 1.0392x over previous
#include <cuda_runtime.h>

// SkelConv v9: CG=2 / U=8, 4 CTAs/SM (16 warps) spill-free, with per-warp
// ci-loop rotation to desynchronize LDG bursts (L1tex queue flattening).
// Parity-shifted accumulators (zero pack MOVs in hot loop).

#define C_IN   103
#define C_OUT  206
#define KK     15
#define TLEN   8192
#define NB     32
#define TPB    128
#define U      8
#define TT     256          // 32 lanes * 8
#define CG     2

typedef unsigned long long u64;

__device__ __forceinline__ u64 pack2(float lo, float hi) {
    u64 r;
    asm("mov.b64 %0, {%1, %2};" : "=l"(r) : "f"(lo), "f"(hi));
    return r;
}
__device__ __forceinline__ void unpack2(u64 v, float& lo, float& hi) {
    asm("mov.b64 {%0, %1}, %2;" : "=f"(lo), "=f"(hi) : "l"(v));
}
__device__ __forceinline__ void ffma2(u64& d, u64 a, u64 b) {
    asm("fma.rn.f32x2 %0, %1, %2, %0;" : "+l"(d) : "l"(a), "l"(b));
}

// y = 0..25: 0,1 = root halves (7 out ch each), y>=2 -> joint j=y-1 (8 out ch)
__device__ __forceinline__ void jp(int y, int& i0, int& iw, int& o0, int& ow) {
    if (y == 0)      { i0 = 0;  iw = 11; o0 = 0; ow = 7; }
    else if (y == 1) { i0 = 0;  iw = 11; o0 = 7; ow = 7; }
    else {
        const int j = y - 1;
        o0 = 14 + (j - 1) * 8; ow = 8;
        if (j == 1)       { i0 = 0;              iw = 15; }
        else if (j == 24) { i0 = 95;             iw = 8;  }
        else              { i0 = 7 + (j - 2) * 4; iw = 12; }
    }
}

__global__ void __launch_bounds__(TPB, 4)
skel_conv9_kernel(const float* __restrict__ x,
                  const float* __restrict__ w,
                  const float* __restrict__ bias,
                  const float* __restrict__ mask,
                  float* __restrict__ out)
{
    int i0, iw, o0, ow;
    jp(blockIdx.y, i0, iw, o0, ow);

    const int b   = blockIdx.z;
    const int tid = threadIdx.x;

    // wsh[ci][co][q] = {w(2q),w(2q), w(2q+1),w(2q+1)} masked (k=15 slot -> 0).
    __shared__ float4 wsh[15][8][8];
    {
        const int total = iw * 64;
        for (int idx = tid; idx < total; idx += TPB) {
            const int q  = idx & 7;
            const int co = (idx >> 3) & 7;
            const int ci = idx >> 6;
            float a = 0.0f, c = 0.0f;
            if (co < ow) {
                const int gi = ((o0 + co) * C_IN + (i0 + ci)) * KK;
                a = w[gi + 2 * q] * mask[gi + 2 * q];
                if (2 * q + 1 < KK) c = w[gi + 2 * q + 1] * mask[gi + 2 * q + 1];
            }
            wsh[ci][co][q] = make_float4(a, a, c, c);
        }
    }
    __syncthreads();

    const int g      = tid >> 5;          // warp id 0..3 -> co-pair
    const int lane   = tid & 31;
    const int cobase = g * CG;
    const int T0     = blockIdx.x * TT + lane * U;

    // accA[c][p]: odd taps, outputs {T0+2p, T0+2p+1}, p=0..3
    // accB[c][j]: even taps, outputs {T0+2j-1, T0+2j}, j=0..4
    u64 accA[CG][4], accB[CG][5];
#pragma unroll
    for (int c = 0; c < CG; c++) {
#pragma unroll
        for (int p = 0; p < 4; p++) accA[c][p] = 0ull;
#pragma unroll
        for (int j = 0; j < 5; j++) accB[c][j] = 0ull;
    }

    const bool interior = (T0 >= 8) && (T0 + 16 <= TLEN);
    const float* base = x + (size_t)b * C_IN * TLEN;

    // Desync: each warp (and CTA) starts the ci loop at a rotated position.
    const int rot = ((g + blockIdx.x) & 3) * (iw >> 2);
    int cp = rot;

    for (int it = 0; it < iw; it++) {
        const float* xrow = base + (size_t)(i0 + cp) * TLEN;

        // xe[i] = {x[T0-8+2i], x[T0-8+2i+1]}, i = 0..11 (window [T0-8, T0+16))
        u64 xe[12];
        if (interior) {
            const ulonglong2* xq =
                reinterpret_cast<const ulonglong2*>(xrow + T0 - 8);
#pragma unroll
            for (int q = 0; q < 6; q++) {
                const ulonglong2 v = xq[q];
                xe[2 * q]     = v.x;
                xe[2 * q + 1] = v.y;
            }
        } else {
#pragma unroll
            for (int i = 0; i < 12; i++) {
                const int t = T0 - 8 + 2 * i;
                const float lo = (t >= 0 && t < TLEN) ? xrow[t] : 0.0f;
                const float hi = (t + 1 >= 0 && t + 1 < TLEN) ? xrow[t + 1] : 0.0f;
                xe[i] = pack2(lo, hi);
            }
        }

#pragma unroll
        for (int c = 0; c < CG; c++) {
            const ulonglong2* wq =
                reinterpret_cast<const ulonglong2*>(&wsh[cp][cobase + c][0]);
#pragma unroll
            for (int q = 0; q < 8; q++) {
                const ulonglong2 wv = wq[q];  // .x = dup w(2q), .y = dup w(2q+1)
                // even tap k=2q -> accB[j] uses xe[q+j], j=0..4
#pragma unroll
                for (int jj = 0; jj < 5; jj++) ffma2(accB[c][jj], wv.x, xe[q + jj]);
                // odd tap k=2q+1 (k<15) -> accA[p] uses xe[q+1+p], p=0..3
                if (q < 7) {
#pragma unroll
                    for (int p = 0; p < 4; p++) ffma2(accA[c][p], wv.y, xe[q + 1 + p]);
                }
            }
        }

        cp++;
        if (cp == iw) cp = 0;
    }

    // Combine parities + bias + store (8 outputs per co).
#pragma unroll
    for (int c = 0; c < CG; c++) {
        const int co = cobase + c;
        if (co < ow) {
            const float bv = bias[o0 + co];
            float* ob = out + ((size_t)b * C_OUT + (o0 + co)) * TLEN + T0;
            float aLo[4], aHi[4], bLo[5], bHi[5];
#pragma unroll
            for (int p = 0; p < 4; p++) unpack2(accA[c][p], aLo[p], aHi[p]);
#pragma unroll
            for (int j = 0; j < 5; j++) unpack2(accB[c][j], bLo[j], bHi[j]);
            float4 r0, r1;
            r0.x = aLo[0] + bHi[0] + bv;
            r0.y = aHi[0] + bLo[1] + bv;
            r0.z = aLo[1] + bHi[1] + bv;
            r0.w = aHi[1] + bLo[2] + bv;
            r1.x = aLo[2] + bHi[2] + bv;
            r1.y = aHi[2] + bLo[3] + bv;
            r1.z = aLo[3] + bHi[3] + bv;
            r1.w = aHi[3] + bLo[4] + bv;
            *reinterpret_cast<float4*>(ob)     = r0;
            *reinterpret_cast<float4*>(ob + 4) = r1;
        }
    }
}

extern "C" void kernel_launch(void* const* d_in, const int* in_sizes, int n_in,
                              void* d_out, int out_size)
{
    (void)in_sizes; (void)n_in; (void)out_size;
    const float* x    = (const float*)d_in[0];
    const float* w    = (const float*)d_in[1];
    const float* bias = (const float*)d_in[2];
    const float* mask = (const float*)d_in[3];
    float* out = (float*)d_out;

    dim3 grid(TLEN / TT, 26, NB);
    skel_conv9_kernel<<<grid, TPB>>>(x, w, bias, mask, out);
}

// round 10
// speedup vs baseline: 1.0470x; 1.0075x over previous
#include <cuda_runtime.h>

// SkelConv v10: co in lane dimension for warp-level LDG dedup.
// Warp = 8 out-channels x 4 time-segments; lane = tseg*8 + co. The 8 co-lanes
// of a tseg read IDENTICAL x addresses (dedup -> ~2 wavefronts per LDG.128
// instead of 8). Weights laid out [ci][q][co] so co is 16B-contiguous.
// CG=1, U=16, parity-shifted accumulators (no pack MOVs).

#define C_IN   103
#define C_OUT  206
#define KK     15
#define TLEN   8192
#define NB     32
#define TPB    128
#define U      16
#define TT     256          // 4 warps * 4 tsegs * 16

typedef unsigned long long u64;

__device__ __forceinline__ u64 pack2(float lo, float hi) {
    u64 r;
    asm("mov.b64 %0, {%1, %2};" : "=l"(r) : "f"(lo), "f"(hi));
    return r;
}
__device__ __forceinline__ void unpack2(u64 v, float& lo, float& hi) {
    asm("mov.b64 {%0, %1}, %2;" : "=f"(lo), "=f"(hi) : "l"(v));
}
__device__ __forceinline__ void ffma2(u64& d, u64 a, u64 b) {
    asm("fma.rn.f32x2 %0, %1, %2, %0;" : "+l"(d) : "l"(a), "l"(b));
}

// y = 0..25: 0,1 = root halves (7 out ch each), y>=2 -> joint j=y-1 (8 out ch)
__device__ __forceinline__ void jp(int y, int& i0, int& iw, int& o0, int& ow) {
    if (y == 0)      { i0 = 0;  iw = 11; o0 = 0; ow = 7; }
    else if (y == 1) { i0 = 0;  iw = 11; o0 = 7; ow = 7; }
    else {
        const int j = y - 1;
        o0 = 14 + (j - 1) * 8; ow = 8;
        if (j == 1)       { i0 = 0;              iw = 15; }
        else if (j == 24) { i0 = 95;             iw = 8;  }
        else              { i0 = 7 + (j - 2) * 4; iw = 12; }
    }
}

__global__ void __launch_bounds__(TPB, 5)
skel_conv10_kernel(const float* __restrict__ x,
                   const float* __restrict__ w,
                   const float* __restrict__ bias,
                   const float* __restrict__ mask,
                   float* __restrict__ out)
{
    int i0, iw, o0, ow;
    jp(blockIdx.y, i0, iw, o0, ow);

    const int b   = blockIdx.z;
    const int tid = threadIdx.x;

    // wsh[ci][q][co] = {w(2q),w(2q), w(2q+1),w(2q+1)} for channel co (masked).
    // co is contiguous (16B stride) -> 8-lane co-spread LDS.128 spans 128B.
    __shared__ float4 wsh[15][8][8];
    {
        const int total = iw * 64;
        for (int idx = tid; idx < total; idx += TPB) {
            const int co = idx & 7;
            const int q  = (idx >> 3) & 7;
            const int ci = idx >> 6;
            float a = 0.0f, c = 0.0f;
            if (co < ow) {
                const int gi = ((o0 + co) * C_IN + (i0 + ci)) * KK;
                a = w[gi + 2 * q] * mask[gi + 2 * q];
                if (2 * q + 1 < KK) c = w[gi + 2 * q + 1] * mask[gi + 2 * q + 1];
            }
            wsh[ci][q][co] = make_float4(a, a, c, c);
        }
    }
    __syncthreads();

    const int warp = tid >> 5;
    const int lane = tid & 31;
    const int co   = lane & 7;
    const int tseg = lane >> 3;
    const int T0   = blockIdx.x * TT + warp * 64 + tseg * U;

    // accA[p]: odd taps, outputs {T0+2p, T0+2p+1}, p=0..7
    // accB[j]: even taps, outputs {T0+2j-1, T0+2j}, j=0..8
    u64 accA[8], accB[9];
#pragma unroll
    for (int p = 0; p < 8; p++) accA[p] = 0ull;
#pragma unroll
    for (int j = 0; j < 9; j++) accB[j] = 0ull;

    const bool interior = (T0 >= 8) && (T0 + 24 <= TLEN);
    const float* base = x + (size_t)b * C_IN * TLEN;

    for (int ci = 0; ci < iw; ci++) {
        const float* xrow = base + (size_t)(i0 + ci) * TLEN;

        // xe[i] = {x[T0-8+2i], x[T0-8+2i+1]}, i = 0..15 (window [T0-8, T0+24))
        u64 xe[16];
        if (interior) {
            const ulonglong2* xq =
                reinterpret_cast<const ulonglong2*>(xrow + T0 - 8);
#pragma unroll
            for (int q = 0; q < 8; q++) {
                const ulonglong2 v = xq[q];
                xe[2 * q]     = v.x;
                xe[2 * q + 1] = v.y;
            }
        } else {
#pragma unroll
            for (int i = 0; i < 16; i++) {
                const int t = T0 - 8 + 2 * i;
                const float lo = (t >= 0 && t < TLEN) ? xrow[t] : 0.0f;
                const float hi = (t + 1 >= 0 && t + 1 < TLEN) ? xrow[t + 1] : 0.0f;
                xe[i] = pack2(lo, hi);
            }
        }

        // Weights for this lane's co: stride between q entries is 8 float4.
        const ulonglong2* wq =
            reinterpret_cast<const ulonglong2*>(&wsh[ci][0][co]);
#pragma unroll
        for (int q = 0; q < 8; q++) {
            const ulonglong2 wv = wq[q * 8];  // .x = dup w(2q), .y = dup w(2q+1)
            // even tap k=2q -> accB[j] uses xe[q+j], j=0..8
#pragma unroll
            for (int jj = 0; jj < 9; jj++) ffma2(accB[jj], wv.x, xe[q + jj]);
            // odd tap k=2q+1 (k<15) -> accA[p] uses xe[q+1+p], p=0..7
            if (q < 7) {
#pragma unroll
                for (int p = 0; p < 8; p++) ffma2(accA[p], wv.y, xe[q + 1 + p]);
            }
        }
    }

    // Combine parities + bias + store (16 outputs).
    if (co < ow) {
        const float bv = bias[o0 + co];
        float* ob = out + ((size_t)b * C_OUT + (o0 + co)) * TLEN + T0;
        float aLo[8], aHi[8], bLo[9], bHi[9];
#pragma unroll
        for (int p = 0; p < 8; p++) unpack2(accA[p], aLo[p], aHi[p]);
#pragma unroll
        for (int j = 0; j < 9; j++) unpack2(accB[j], bLo[j], bHi[j]);
#pragma unroll
        for (int p = 0; p < 8; p += 2) {
            float4 r;
            r.x = aLo[p]     + bHi[p]     + bv;   // out[T0+2p]
            r.y = aHi[p]     + bLo[p + 1] + bv;   // out[T0+2p+1]
            r.z = aLo[p + 1] + bHi[p + 1] + bv;   // out[T0+2p+2]
            r.w = aHi[p + 1] + bLo[p + 2] + bv;   // out[T0+2p+3]
            *reinterpret_cast<float4*>(ob + 2 * p) = r;
        }
    }
}

extern "C" void kernel_launch(void* const* d_in, const int* in_sizes, int n_in,
                              void* d_out, int out_size)
{
    (void)in_sizes; (void)n_in; (void)out_size;
    const float* x    = (const float*)d_in[0];
    const float* w    = (const float*)d_in[1];
    const float* bias = (const float*)d_in[2];
    const float* mask = (const float*)d_in[3];
    float* out = (float*)d_out;

    dim3 grid(TLEN / TT, 26, NB);
    skel_conv10_kernel<<<grid, TPB>>>(x, w, bias, mask, out);
}